// round 14
// baseline (speedup 1.0000x reference)
#include <cuda_runtime.h>
#include <cuda_bf16.h>
#include <cstdint>

#define MAXN  100000
#define MAXE  2000000
#define DH    256
#define DIN   128

// Scratch (static device globals — no allocation allowed)
__device__ float g_dinv[MAXN];
__device__ float g_buf1[(size_t)MAXN * DH];
__device__ float g_buf2[(size_t)MAXN * DH];
__device__ int   g_cnt[MAXN];
__device__ int   g_off[MAXN + 1];
__device__ int   g_cur[MAXN];
__device__ int   g_src[MAXE];
__device__ float g_wt1[DH * DIN];   // W1^T [256][128]
__device__ float g_wt2[DH * DH];    // W2^T [256][256]

// ---------------------------------------------------------------------------
// CSR build
// ---------------------------------------------------------------------------
__global__ void count_kernel(const int* __restrict__ edst, int e, int* __restrict__ cnt) {
    int i = blockIdx.x * blockDim.x + threadIdx.x;
    if (i < e) atomicAdd(&cnt[edst[i]], 1);
}

__global__ void __launch_bounds__(1024)
scan_kernel(const int* __restrict__ cnt, int* __restrict__ off, int* __restrict__ cur,
            float* __restrict__ dinv, int n) {
    __shared__ int ssum[1024];
    const int tid = threadIdx.x;
    const int chunk = (n + 1023) >> 10;
    const int begin = tid * chunk;
    const int end   = min(begin + chunk, n);

    int mysum = 0;
    for (int i = begin; i < end; i++) mysum += cnt[i];
    ssum[tid] = mysum;
    __syncthreads();
    for (int d = 1; d < 1024; d <<= 1) {
        int add = (tid >= d) ? ssum[tid - d] : 0;
        __syncthreads();
        ssum[tid] += add;
        __syncthreads();
    }
    int run = ssum[tid] - mysum;
    for (int i = begin; i < end; i++) {
        int c = cnt[i];
        off[i] = run;
        cur[i] = run;
        dinv[i] = rsqrtf(1.0f + (float)c);
        run += c;
    }
    if (tid == 1023) off[n] = ssum[1023];
}

__global__ void fill_kernel(const int* __restrict__ esrc, const int* __restrict__ edst,
                            int e, int* __restrict__ cur, int* __restrict__ sorted) {
    int i = blockIdx.x * blockDim.x + threadIdx.x;
    if (i < e) {
        int d = edst[i];
        int pos = atomicAdd(&cur[d], 1);
        sorted[pos] = esrc[i];
    }
}

// ---------------------------------------------------------------------------
// Transpose W [K][256] -> Wt [256][K]
// ---------------------------------------------------------------------------
template <int K>
__global__ void transpose_kernel(const float* __restrict__ W, float* __restrict__ Wt) {
    __shared__ float t[32][33];
    int bx = blockIdx.x * 32;   // N dim
    int by = blockIdx.y * 32;   // K dim
#pragma unroll
    for (int i = 0; i < 4; i++)
        t[threadIdx.y + i * 8][threadIdx.x] =
            W[(size_t)(by + threadIdx.y + i * 8) * DH + bx + threadIdx.x];
    __syncthreads();
#pragma unroll
    for (int i = 0; i < 4; i++)
        Wt[(size_t)(bx + threadIdx.y + i * 8) * K + by + threadIdx.x] =
            t[threadIdx.x][threadIdx.y + i * 8];
}

// ---------------------------------------------------------------------------
// bf16 split helpers (3-term split: x = hi + lo + O(2^-18 x))
// ---------------------------------------------------------------------------
__device__ __forceinline__ uint32_t bpack(__nv_bfloat16 a, __nv_bfloat16 b) {
    __nv_bfloat162 p(a, b);
    return *reinterpret_cast<uint32_t*>(&p);
}
__device__ __forceinline__ void split2(float f0, float f1, uint32_t& h, uint32_t& l) {
    __nv_bfloat16 h0 = __float2bfloat16(f0);
    __nv_bfloat16 h1 = __float2bfloat16(f1);
    __nv_bfloat16 l0 = __float2bfloat16(f0 - __bfloat162float(h0));
    __nv_bfloat16 l1 = __float2bfloat16(f1 - __bfloat162float(h1));
    h = bpack(h0, h1);
    l = bpack(l0, l1);
}

__device__ __forceinline__ void mma_bf16(float* c, const uint32_t* a, uint32_t b0, uint32_t b1) {
    asm volatile(
        "mma.sync.aligned.m16n8k16.row.col.f32.bf16.bf16.f32 "
        "{%0,%1,%2,%3}, {%4,%5,%6,%7}, {%8,%9}, {%0,%1,%2,%3};"
        : "+f"(c[0]), "+f"(c[1]), "+f"(c[2]), "+f"(c[3])
        : "r"(a[0]), "r"(a[1]), "r"(a[2]), "r"(a[3]), "r"(b0), "r"(b1));
}

// ---------------------------------------------------------------------------
// Tensor-core GEMM: bf16 m16n8k16 + 3-term split, fragment-layout smem.
//   MODE 0: C = dinv[m] * relu(acc + b);  MODE 1: C = relu(acc + b)
// BM=64, BN=256(full), BK=16; 256 threads = 8 warps (2x4), warp tile 32x64.
// ---------------------------------------------------------------------------
#define BMM     64
#define KPS     12
#define A_WORDS (64 * KPS)
#define B_WORDS (256 * KPS)
#define BMMA_SMEM ((2 * A_WORDS * 2 + 2 * B_WORDS * 2) * 4)

template <int K, int MODE>
__global__ void __launch_bounds__(256, 2)
gemm_bmma_kernel(const float* __restrict__ A, const float* __restrict__ Wt,
                 const float* __restrict__ dinv, const float* __restrict__ bias,
                 float* __restrict__ C, int M) {
    constexpr int NT = K / 16;
    extern __shared__ uint32_t smw[];
    uint32_t* AsH = smw;
    uint32_t* AsL = smw + 2 * A_WORDS;
    uint32_t* BsH = smw + 4 * A_WORDS;
    uint32_t* BsL = BsH + 2 * B_WORDS;

    const int tid  = threadIdx.x;
    const int bm   = blockIdx.x * BMM;
    const int wid  = tid >> 5;
    const int lane = tid & 31;
    const int wm   = wid >> 2;
    const int wn   = wid & 3;
    const int g    = lane >> 2;
    const int t    = lane & 3;

    const int arow = tid >> 2;
    const int akc  = (tid & 3) * 4;
    const bool aok = (bm + arow) < M;
    const float* aP = &A[(size_t)(bm + arow) * K + akc];
    const float* bP = &Wt[(size_t)tid * K];

    float acc[2][8][4];
#pragma unroll
    for (int i = 0; i < 2; i++)
#pragma unroll
        for (int j = 0; j < 8; j++)
#pragma unroll
            for (int q = 0; q < 4; q++) acc[i][j][q] = 0.0f;

    float4 aS;
    float4 bS[4];

    aS = aok ? *reinterpret_cast<const float4*>(aP) : make_float4(0.f, 0.f, 0.f, 0.f);
#pragma unroll
    for (int j = 0; j < 4; j++) bS[j] = *reinterpret_cast<const float4*>(bP + j * 4);
    {
        uint32_t hA, lA, hB, lB;
        split2(aS.x, aS.y, hA, lA);
        split2(aS.z, aS.w, hB, lB);
        const int ab = arow * KPS + (akc >> 1);
        *reinterpret_cast<uint2*>(&AsH[ab]) = make_uint2(hA, hB);
        *reinterpret_cast<uint2*>(&AsL[ab]) = make_uint2(lA, lB);
#pragma unroll
        for (int j = 0; j < 4; j++) {
            split2(bS[j].x, bS[j].y, hA, lA);
            split2(bS[j].z, bS[j].w, hB, lB);
            const int bb = tid * KPS + j * 2;
            *reinterpret_cast<uint2*>(&BsH[bb]) = make_uint2(hA, hB);
            *reinterpret_cast<uint2*>(&BsL[bb]) = make_uint2(lA, lB);
        }
    }
    __syncthreads();

    for (int tt = 0; tt < NT; tt++) {
        const int cb  = tt & 1;
        const int nxb = cb ^ 1;
        const bool has_next = (tt + 1 < NT);

        if (has_next) {
            const int k0 = (tt + 1) * 16;
            aS = aok ? *reinterpret_cast<const float4*>(aP + k0)
                     : make_float4(0.f, 0.f, 0.f, 0.f);
#pragma unroll
            for (int j = 0; j < 4; j++)
                bS[j] = *reinterpret_cast<const float4*>(bP + k0 + j * 4);
        }

        const uint32_t* ah = AsH + cb * A_WORDS;
        const uint32_t* al = AsL + cb * A_WORDS;
        const uint32_t* bh = BsH + cb * B_WORDS;
        const uint32_t* bl = BsL + cb * B_WORDS;

        uint32_t aHf[2][4], aLf[2][4];
#pragma unroll
        for (int mt = 0; mt < 2; mt++) {
            const int r0 = (wm * 32 + mt * 16 + g) * KPS;
            aHf[mt][0] = ah[r0 + t];
            aHf[mt][1] = ah[r0 + 8 * KPS + t];
            aHf[mt][2] = ah[r0 + t + 4];
            aHf[mt][3] = ah[r0 + 8 * KPS + t + 4];
            aLf[mt][0] = al[r0 + t];
            aLf[mt][1] = al[r0 + 8 * KPS + t];
            aLf[mt][2] = al[r0 + t + 4];
            aLf[mt][3] = al[r0 + 8 * KPS + t + 4];
        }
#pragma unroll
        for (int nt = 0; nt < 8; nt++) {
            const int nbi = (wn * 64 + nt * 8 + g) * KPS;
            const uint32_t b0H = bh[nbi + t];
            const uint32_t b1H = bh[nbi + t + 4];
            const uint32_t b0L = bl[nbi + t];
            const uint32_t b1L = bl[nbi + t + 4];
#pragma unroll
            for (int mt = 0; mt < 2; mt++) {
                mma_bf16(acc[mt][nt], aHf[mt], b0L, b1L);
                mma_bf16(acc[mt][nt], aLf[mt], b0H, b1H);
                mma_bf16(acc[mt][nt], aHf[mt], b0H, b1H);
            }
        }

        if (has_next) {
            uint32_t hA, lA, hB, lB;
            split2(aS.x, aS.y, hA, lA);
            split2(aS.z, aS.w, hB, lB);
            const int ab = nxb * A_WORDS + arow * KPS + (akc >> 1);
            *reinterpret_cast<uint2*>(&AsH[ab]) = make_uint2(hA, hB);
            *reinterpret_cast<uint2*>(&AsL[ab]) = make_uint2(lA, lB);
#pragma unroll
            for (int j = 0; j < 4; j++) {
                split2(bS[j].x, bS[j].y, hA, lA);
                split2(bS[j].z, bS[j].w, hB, lB);
                const int bb = nxb * B_WORDS + tid * KPS + j * 2;
                *reinterpret_cast<uint2*>(&BsH[bb]) = make_uint2(hA, hB);
                *reinterpret_cast<uint2*>(&BsL[bb]) = make_uint2(lA, lB);
            }
            __syncthreads();
        }
    }

#pragma unroll
    for (int mt = 0; mt < 2; mt++) {
        const int r0 = bm + wm * 32 + mt * 16 + g;
        const int r1 = r0 + 8;
        float s0 = 1.0f, s1 = 1.0f;
        if (MODE == 0) {
            if (r0 < M) s0 = dinv[r0];
            if (r1 < M) s1 = dinv[r1];
        }
#pragma unroll
        for (int nt = 0; nt < 8; nt++) {
            const int c0 = wn * 64 + nt * 8 + 2 * t;
            const float bb0 = bias[c0];
            const float bb1 = bias[c0 + 1];
            float v00 = fmaxf(acc[mt][nt][0] + bb0, 0.0f) * s0;
            float v01 = fmaxf(acc[mt][nt][1] + bb1, 0.0f) * s0;
            float v10 = fmaxf(acc[mt][nt][2] + bb0, 0.0f) * s1;
            float v11 = fmaxf(acc[mt][nt][3] + bb1, 0.0f) * s1;
            if (r0 < M)
                *reinterpret_cast<float2*>(&C[(size_t)r0 * DH + c0]) = make_float2(v00, v01);
            if (r1 < M)
                *reinterpret_cast<float2*>(&C[(size_t)r1 * DH + c0]) = make_float2(v10, v11);
        }
    }
}

// ---------------------------------------------------------------------------
// Gather layer 1: TWO warps per node, float2 granularity, unroll x8.
//   z1[d] = dinv[d] * ( sum_{s in N(d)} dinv[s]*x[s]  +  dinv[d]*x[d] )
// Lane owns float2 index (half*32 + lane) of 64 float2s (128 floats).
// ---------------------------------------------------------------------------
__global__ void __launch_bounds__(256)
gather_x_kernel(const float* __restrict__ x, const int* __restrict__ off,
                const int* __restrict__ sorted, const float* __restrict__ dinv,
                float* __restrict__ z, int n) {
    int gwarp = (blockIdx.x * blockDim.x + threadIdx.x) >> 5;
    int lane  = threadIdx.x & 31;
    int d     = gwarp >> 1;
    if (d >= n) return;
    const int foff = ((gwarp & 1) << 5) + lane;   // 0..63
    const int s0 = off[d];
    const int s1 = off[d + 1];
    const float dd = dinv[d];

    const float2* base = reinterpret_cast<const float2*>(x);
    float2 a = __ldg(base + (size_t)d * 64 + foff);
    float2 v = make_float2(a.x * dd, a.y * dd);

    int j = s0;
    for (; j + 7 < s1; j += 8) {
        int   si[8];
        float ds[8];
        float2 r[8];
#pragma unroll
        for (int q = 0; q < 8; q++) si[q] = __ldg(&sorted[j + q]);
#pragma unroll
        for (int q = 0; q < 8; q++) ds[q] = __ldg(&dinv[si[q]]);
#pragma unroll
        for (int q = 0; q < 8; q++) r[q] = __ldg(base + (size_t)si[q] * 64 + foff);
#pragma unroll
        for (int q = 0; q < 8; q++) {
            v.x = fmaf(r[q].x, ds[q], v.x);
            v.y = fmaf(r[q].y, ds[q], v.y);
        }
    }
    for (; j < s1; j++) {
        int s = __ldg(&sorted[j]);
        float dsv = __ldg(&dinv[s]);
        float2 r = __ldg(base + (size_t)s * 64 + foff);
        v.x = fmaf(r.x, dsv, v.x);
        v.y = fmaf(r.y, dsv, v.y);
    }
    v.x *= dd; v.y *= dd;
    reinterpret_cast<float2*>(z)[(size_t)d * 64 + foff] = v;
}

// ---------------------------------------------------------------------------
// Gather layer 2: FOUR warps per node, float2 granularity, unroll x8.
//   z2[d] = dinv[d] * ( sum_{s in N(d)} hs[s]  +  hs[d] )   (hs pre-scaled)
// Lane owns float2 index (q*32 + lane) of 128 float2s (256 floats).
// ---------------------------------------------------------------------------
__global__ void __launch_bounds__(256)
gather_h_kernel(const float* __restrict__ hs, const int* __restrict__ off,
                const int* __restrict__ sorted, const float* __restrict__ dinv,
                float* __restrict__ z, int n) {
    int gwarp = (blockIdx.x * blockDim.x + threadIdx.x) >> 5;
    int lane  = threadIdx.x & 31;
    int d     = gwarp >> 2;
    if (d >= n) return;
    const int foff = ((gwarp & 3) << 5) + lane;   // 0..127
    const int s0 = off[d];
    const int s1 = off[d + 1];

    const float2* base = reinterpret_cast<const float2*>(hs);
    float2 v = __ldg(base + (size_t)d * 128 + foff);

    int j = s0;
    for (; j + 7 < s1; j += 8) {
        int    si[8];
        float2 r[8];
#pragma unroll
        for (int q = 0; q < 8; q++) si[q] = __ldg(&sorted[j + q]);
#pragma unroll
        for (int q = 0; q < 8; q++) r[q] = __ldg(base + (size_t)si[q] * 128 + foff);
        float2 p0 = make_float2((r[0].x + r[1].x) + (r[2].x + r[3].x),
                                (r[0].y + r[1].y) + (r[2].y + r[3].y));
        float2 p1 = make_float2((r[4].x + r[5].x) + (r[6].x + r[7].x),
                                (r[4].y + r[5].y) + (r[6].y + r[7].y));
        v.x += p0.x + p1.x;
        v.y += p0.y + p1.y;
    }
    for (; j < s1; j++) {
        int s = __ldg(&sorted[j]);
        float2 a = __ldg(base + (size_t)s * 128 + foff);
        v.x += a.x; v.y += a.y;
    }

    const float dd = dinv[d];
    v.x *= dd; v.y *= dd;
    reinterpret_cast<float2*>(z)[(size_t)d * 128 + foff] = v;
}

// ---------------------------------------------------------------------------
// Launch
// ---------------------------------------------------------------------------
extern "C" void kernel_launch(void* const* d_in, const int* in_sizes, int n_in,
                              void* d_out, int out_size) {
    const float* x  = (const float*)d_in[0];
    const int*   ei = (const int*)d_in[1];
    const float* W1 = (const float*)d_in[2];
    const float* b1 = (const float*)d_in[3];
    const float* W2 = (const float*)d_in[4];
    const float* b2 = (const float*)d_in[5];
    float* out = (float*)d_out;

    const int n = in_sizes[0] / DIN;
    const int e = in_sizes[1] / 2;
    const int* esrc = ei;
    const int* edst = ei + e;

    float *dinv, *buf1, *buf2, *wt1, *wt2;
    int *cnt, *off, *cur, *srt;
    cudaGetSymbolAddress((void**)&dinv, g_dinv);
    cudaGetSymbolAddress((void**)&buf1, g_buf1);
    cudaGetSymbolAddress((void**)&buf2, g_buf2);
    cudaGetSymbolAddress((void**)&cnt,  g_cnt);
    cudaGetSymbolAddress((void**)&off,  g_off);
    cudaGetSymbolAddress((void**)&cur,  g_cur);
    cudaGetSymbolAddress((void**)&srt,  g_src);
    cudaGetSymbolAddress((void**)&wt1,  g_wt1);
    cudaGetSymbolAddress((void**)&wt2,  g_wt2);

    cudaFuncSetAttribute(gemm_bmma_kernel<DIN, 0>, cudaFuncAttributeMaxDynamicSharedMemorySize, BMMA_SMEM);
    cudaFuncSetAttribute(gemm_bmma_kernel<DH, 1>,  cudaFuncAttributeMaxDynamicSharedMemorySize, BMMA_SMEM);

    const int T = 256;
    const int e_blk  = (e + T - 1) / T;
    const int gx_blk = (2 * n + (T / 32) - 1) / (T / 32);   // 2 warps / node
    const int gh_blk = (4 * n + (T / 32) - 1) / (T / 32);   // 4 warps / node
    const int gemm_blk = (n + BMM - 1) / BMM;

    // ----- CSR build -----
    cudaMemsetAsync(cnt, 0, (size_t)n * sizeof(int));
    count_kernel<<<e_blk, T>>>(edst, e, cnt);
    scan_kernel<<<1, 1024>>>(cnt, off, cur, dinv, n);
    fill_kernel<<<e_blk, T>>>(esrc, edst, e, cur, srt);

    // ----- weight transposes -----
    transpose_kernel<DIN><<<dim3(DH / 32, DIN / 32), dim3(32, 8)>>>(W1, wt1);
    transpose_kernel<DH><<<dim3(DH / 32, DH / 32), dim3(32, 8)>>>(W2, wt2);

    // ----- Layer 1 (aggregate-first: 128-dim gather) -----
    gather_x_kernel<<<gx_blk, T>>>(x, off, srt, dinv, buf1, n);
    gemm_bmma_kernel<DIN, 0><<<gemm_blk, T, BMMA_SMEM>>>(buf1, wt1, dinv, b1, buf2, n);

    // ----- Layer 2 (aggregate-then-transform) -----
    gather_h_kernel<<<gh_blk, T>>>(buf2, off, srt, dinv, buf1, n);
    gemm_bmma_kernel<DH, 1><<<gemm_blk, T, BMMA_SMEM>>>(buf1, wt2, dinv, b2, out, n);
}

// round 16
// speedup vs baseline: 1.0548x; 1.0548x over previous
#include <cuda_runtime.h>
#include <cuda_bf16.h>
#include <cstdint>

#define MAXN  100000
#define MAXE  2000000
#define DH    256
#define DIN   128

// Scratch (static device globals — no allocation allowed)
__device__ float g_dinv[MAXN];
__device__ float g_buf1[(size_t)MAXN * DH];
__device__ float g_buf2[(size_t)MAXN * DH];
__device__ int   g_cnt[MAXN];
__device__ int   g_off[MAXN + 1];
__device__ int   g_cur[MAXN];
__device__ int   g_src[MAXE];
__device__ float g_wt1[DH * DIN];   // W1^T [256][128]
__device__ float g_wt2[DH * DH];    // W2^T [256][256]

// ---------------------------------------------------------------------------
// CSR build
// ---------------------------------------------------------------------------
__global__ void count_kernel(const int* __restrict__ edst, int e, int* __restrict__ cnt) {
    int i = blockIdx.x * blockDim.x + threadIdx.x;
    if (i < e) atomicAdd(&cnt[edst[i]], 1);
}

__global__ void __launch_bounds__(1024)
scan_kernel(const int* __restrict__ cnt, int* __restrict__ off, int* __restrict__ cur,
            float* __restrict__ dinv, int n) {
    __shared__ int ssum[1024];
    const int tid = threadIdx.x;
    const int chunk = (n + 1023) >> 10;
    const int begin = tid * chunk;
    const int end   = min(begin + chunk, n);

    int mysum = 0;
    for (int i = begin; i < end; i++) mysum += cnt[i];
    ssum[tid] = mysum;
    __syncthreads();
    for (int d = 1; d < 1024; d <<= 1) {
        int add = (tid >= d) ? ssum[tid - d] : 0;
        __syncthreads();
        ssum[tid] += add;
        __syncthreads();
    }
    int run = ssum[tid] - mysum;
    for (int i = begin; i < end; i++) {
        int c = cnt[i];
        off[i] = run;
        cur[i] = run;
        dinv[i] = rsqrtf(1.0f + (float)c);
        run += c;
    }
    if (tid == 1023) off[n] = ssum[1023];
}

__global__ void fill_kernel(const int* __restrict__ esrc, const int* __restrict__ edst,
                            int e, int* __restrict__ cur, int* __restrict__ sorted) {
    int i = blockIdx.x * blockDim.x + threadIdx.x;
    if (i < e) {
        int d = edst[i];
        int pos = atomicAdd(&cur[d], 1);
        sorted[pos] = esrc[i];
    }
}

// ---------------------------------------------------------------------------
// Transpose W [K][256] -> Wt [256][K]
// ---------------------------------------------------------------------------
template <int K>
__global__ void transpose_kernel(const float* __restrict__ W, float* __restrict__ Wt) {
    __shared__ float t[32][33];
    int bx = blockIdx.x * 32;
    int by = blockIdx.y * 32;
#pragma unroll
    for (int i = 0; i < 4; i++)
        t[threadIdx.y + i * 8][threadIdx.x] =
            W[(size_t)(by + threadIdx.y + i * 8) * DH + bx + threadIdx.x];
    __syncthreads();
#pragma unroll
    for (int i = 0; i < 4; i++)
        Wt[(size_t)(bx + threadIdx.y + i * 8) * K + by + threadIdx.x] =
            t[threadIdx.x][threadIdx.y + i * 8];
}

// ---------------------------------------------------------------------------
// bf16 split helpers (3-term split: x = hi + lo + O(2^-18 x))
// ---------------------------------------------------------------------------
__device__ __forceinline__ uint32_t bpack(__nv_bfloat16 a, __nv_bfloat16 b) {
    __nv_bfloat162 p(a, b);
    return *reinterpret_cast<uint32_t*>(&p);
}
__device__ __forceinline__ void split2(float f0, float f1, uint32_t& h, uint32_t& l) {
    __nv_bfloat16 h0 = __float2bfloat16(f0);
    __nv_bfloat16 h1 = __float2bfloat16(f1);
    __nv_bfloat16 l0 = __float2bfloat16(f0 - __bfloat162float(h0));
    __nv_bfloat16 l1 = __float2bfloat16(f1 - __bfloat162float(h1));
    h = bpack(h0, h1);
    l = bpack(l0, l1);
}

__device__ __forceinline__ void mma_bf16(float* c, const uint32_t* a, uint32_t b0, uint32_t b1) {
    asm volatile(
        "mma.sync.aligned.m16n8k16.row.col.f32.bf16.bf16.f32 "
        "{%0,%1,%2,%3}, {%4,%5,%6,%7}, {%8,%9}, {%0,%1,%2,%3};"
        : "+f"(c[0]), "+f"(c[1]), "+f"(c[2]), "+f"(c[3])
        : "r"(a[0]), "r"(a[1]), "r"(a[2]), "r"(a[3]), "r"(b0), "r"(b1));
}

// ---------------------------------------------------------------------------
// Tensor-core GEMM: bf16 m16n8k16 + 3-term split, fragment-layout smem.
//   MODE 0: C = dinv[m] * relu(acc + b);  MODE 1: C = relu(acc + b)
// BM=64, BN=256(full), BK=16; 256 threads = 8 warps (2x4), warp tile 32x64.
// ---------------------------------------------------------------------------
#define BMM     64
#define KPS     12
#define A_WORDS (64 * KPS)
#define B_WORDS (256 * KPS)
#define BMMA_SMEM ((2 * A_WORDS * 2 + 2 * B_WORDS * 2) * 4)

template <int K, int MODE>
__global__ void __launch_bounds__(256, 2)
gemm_bmma_kernel(const float* __restrict__ A, const float* __restrict__ Wt,
                 const float* __restrict__ dinv, const float* __restrict__ bias,
                 float* __restrict__ C, int M) {
    constexpr int NT = K / 16;
    extern __shared__ uint32_t smw[];
    uint32_t* AsH = smw;
    uint32_t* AsL = smw + 2 * A_WORDS;
    uint32_t* BsH = smw + 4 * A_WORDS;
    uint32_t* BsL = BsH + 2 * B_WORDS;

    const int tid  = threadIdx.x;
    const int bm   = blockIdx.x * BMM;
    const int wid  = tid >> 5;
    const int lane = tid & 31;
    const int wm   = wid >> 2;
    const int wn   = wid & 3;
    const int g    = lane >> 2;
    const int t    = lane & 3;

    const int arow = tid >> 2;
    const int akc  = (tid & 3) * 4;
    const bool aok = (bm + arow) < M;
    const float* aP = &A[(size_t)(bm + arow) * K + akc];
    const float* bP = &Wt[(size_t)tid * K];

    float acc[2][8][4];
#pragma unroll
    for (int i = 0; i < 2; i++)
#pragma unroll
        for (int j = 0; j < 8; j++)
#pragma unroll
            for (int q = 0; q < 4; q++) acc[i][j][q] = 0.0f;

    float4 aS;
    float4 bS[4];

    aS = aok ? *reinterpret_cast<const float4*>(aP) : make_float4(0.f, 0.f, 0.f, 0.f);
#pragma unroll
    for (int j = 0; j < 4; j++) bS[j] = *reinterpret_cast<const float4*>(bP + j * 4);
    {
        uint32_t hA, lA, hB, lB;
        split2(aS.x, aS.y, hA, lA);
        split2(aS.z, aS.w, hB, lB);
        const int ab = arow * KPS + (akc >> 1);
        *reinterpret_cast<uint2*>(&AsH[ab]) = make_uint2(hA, hB);
        *reinterpret_cast<uint2*>(&AsL[ab]) = make_uint2(lA, lB);
#pragma unroll
        for (int j = 0; j < 4; j++) {
            split2(bS[j].x, bS[j].y, hA, lA);
            split2(bS[j].z, bS[j].w, hB, lB);
            const int bb = tid * KPS + j * 2;
            *reinterpret_cast<uint2*>(&BsH[bb]) = make_uint2(hA, hB);
            *reinterpret_cast<uint2*>(&BsL[bb]) = make_uint2(lA, lB);
        }
    }
    __syncthreads();

    for (int tt = 0; tt < NT; tt++) {
        const int cb  = tt & 1;
        const int nxb = cb ^ 1;
        const bool has_next = (tt + 1 < NT);

        if (has_next) {
            const int k0 = (tt + 1) * 16;
            aS = aok ? *reinterpret_cast<const float4*>(aP + k0)
                     : make_float4(0.f, 0.f, 0.f, 0.f);
#pragma unroll
            for (int j = 0; j < 4; j++)
                bS[j] = *reinterpret_cast<const float4*>(bP + k0 + j * 4);
        }

        const uint32_t* ah = AsH + cb * A_WORDS;
        const uint32_t* al = AsL + cb * A_WORDS;
        const uint32_t* bh = BsH + cb * B_WORDS;
        const uint32_t* bl = BsL + cb * B_WORDS;

        uint32_t aHf[2][4], aLf[2][4];
#pragma unroll
        for (int mt = 0; mt < 2; mt++) {
            const int r0 = (wm * 32 + mt * 16 + g) * KPS;
            aHf[mt][0] = ah[r0 + t];
            aHf[mt][1] = ah[r0 + 8 * KPS + t];
            aHf[mt][2] = ah[r0 + t + 4];
            aHf[mt][3] = ah[r0 + 8 * KPS + t + 4];
            aLf[mt][0] = al[r0 + t];
            aLf[mt][1] = al[r0 + 8 * KPS + t];
            aLf[mt][2] = al[r0 + t + 4];
            aLf[mt][3] = al[r0 + 8 * KPS + t + 4];
        }
#pragma unroll
        for (int nt = 0; nt < 8; nt++) {
            const int nbi = (wn * 64 + nt * 8 + g) * KPS;
            const uint32_t b0H = bh[nbi + t];
            const uint32_t b1H = bh[nbi + t + 4];
            const uint32_t b0L = bl[nbi + t];
            const uint32_t b1L = bl[nbi + t + 4];
#pragma unroll
            for (int mt = 0; mt < 2; mt++) {
                mma_bf16(acc[mt][nt], aHf[mt], b0L, b1L);
                mma_bf16(acc[mt][nt], aLf[mt], b0H, b1H);
                mma_bf16(acc[mt][nt], aHf[mt], b0H, b1H);
            }
        }

        if (has_next) {
            uint32_t hA, lA, hB, lB;
            split2(aS.x, aS.y, hA, lA);
            split2(aS.z, aS.w, hB, lB);
            const int ab = nxb * A_WORDS + arow * KPS + (akc >> 1);
            *reinterpret_cast<uint2*>(&AsH[ab]) = make_uint2(hA, hB);
            *reinterpret_cast<uint2*>(&AsL[ab]) = make_uint2(lA, lB);
#pragma unroll
            for (int j = 0; j < 4; j++) {
                split2(bS[j].x, bS[j].y, hA, lA);
                split2(bS[j].z, bS[j].w, hB, lB);
                const int bb = nxb * B_WORDS + tid * KPS + j * 2;
                *reinterpret_cast<uint2*>(&BsH[bb]) = make_uint2(hA, hB);
                *reinterpret_cast<uint2*>(&BsL[bb]) = make_uint2(lA, lB);
            }
            __syncthreads();
        }
    }

#pragma unroll
    for (int mt = 0; mt < 2; mt++) {
        const int r0 = bm + wm * 32 + mt * 16 + g;
        const int r1 = r0 + 8;
        float s0 = 1.0f, s1 = 1.0f;
        if (MODE == 0) {
            if (r0 < M) s0 = dinv[r0];
            if (r1 < M) s1 = dinv[r1];
        }
#pragma unroll
        for (int nt = 0; nt < 8; nt++) {
            const int c0 = wn * 64 + nt * 8 + 2 * t;
            const float bb0 = bias[c0];
            const float bb1 = bias[c0 + 1];
            float v00 = fmaxf(acc[mt][nt][0] + bb0, 0.0f) * s0;
            float v01 = fmaxf(acc[mt][nt][1] + bb1, 0.0f) * s0;
            float v10 = fmaxf(acc[mt][nt][2] + bb0, 0.0f) * s1;
            float v11 = fmaxf(acc[mt][nt][3] + bb1, 0.0f) * s1;
            if (r0 < M)
                *reinterpret_cast<float2*>(&C[(size_t)r0 * DH + c0]) = make_float2(v00, v01);
            if (r1 < M)
                *reinterpret_cast<float2*>(&C[(size_t)r1 * DH + c0]) = make_float2(v10, v11);
        }
    }
}

// ---------------------------------------------------------------------------
// Gather layer 1: ONE warp per node, float4 lanes, unroll x8.
//   z1[d] = dinv[d] * ( sum_{s in N(d)} dinv[s]*x[s]  +  dinv[d]*x[d] )
// ---------------------------------------------------------------------------
__global__ void __launch_bounds__(256)
gather_x_kernel(const float* __restrict__ x, const int* __restrict__ off,
                const int* __restrict__ sorted, const float* __restrict__ dinv,
                float* __restrict__ z, int n) {
    int warp = (blockIdx.x * blockDim.x + threadIdx.x) >> 5;
    int lane = threadIdx.x & 31;
    if (warp >= n) return;
    const int d  = warp;
    const int s0 = off[d];
    const int s1 = off[d + 1];
    const float dd = dinv[d];

    const float4* base = reinterpret_cast<const float4*>(x);
    float4 a = __ldg(base + (size_t)d * 32 + lane);
    float4 v = make_float4(a.x * dd, a.y * dd, a.z * dd, a.w * dd);

    int j = s0;
    for (; j + 7 < s1; j += 8) {
        int   si[8];
        float ds[8];
        float4 r[8];
#pragma unroll
        for (int q = 0; q < 8; q++) si[q] = __ldg(&sorted[j + q]);
#pragma unroll
        for (int q = 0; q < 8; q++) ds[q] = __ldg(&dinv[si[q]]);
#pragma unroll
        for (int q = 0; q < 8; q++) r[q] = __ldg(base + (size_t)si[q] * 32 + lane);
#pragma unroll
        for (int q = 0; q < 8; q++) {
            v.x = fmaf(r[q].x, ds[q], v.x);
            v.y = fmaf(r[q].y, ds[q], v.y);
            v.z = fmaf(r[q].z, ds[q], v.z);
            v.w = fmaf(r[q].w, ds[q], v.w);
        }
    }
    for (; j < s1; j++) {
        int s = __ldg(&sorted[j]);
        float dsv = __ldg(&dinv[s]);
        float4 r = __ldg(base + (size_t)s * 32 + lane);
        v.x = fmaf(r.x, dsv, v.x);
        v.y = fmaf(r.y, dsv, v.y);
        v.z = fmaf(r.z, dsv, v.z);
        v.w = fmaf(r.w, dsv, v.w);
    }
    v.x *= dd; v.y *= dd; v.z *= dd; v.w *= dd;
    reinterpret_cast<float4*>(z)[(size_t)d * 32 + lane] = v;
}

// ---------------------------------------------------------------------------
// Gather layer 2: TWO warps per node, float4 lanes, unroll x8.
//   z2[d] = dinv[d] * ( sum_{s in N(d)} hs[s]  +  hs[d] )   (hs pre-scaled)
// ---------------------------------------------------------------------------
__global__ void __launch_bounds__(256)
gather_h_kernel(const float* __restrict__ hs, const int* __restrict__ off,
                const int* __restrict__ sorted, const float* __restrict__ dinv,
                float* __restrict__ z, int n) {
    int gwarp = (blockIdx.x * blockDim.x + threadIdx.x) >> 5;
    int lane  = threadIdx.x & 31;
    int d     = gwarp >> 1;
    if (d >= n) return;
    const int foff = ((gwarp & 1) << 5) + lane;   // 0..63
    const int s0 = off[d];
    const int s1 = off[d + 1];

    const float4* base = reinterpret_cast<const float4*>(hs);
    float4 v = __ldg(base + (size_t)d * 64 + foff);

    int j = s0;
    for (; j + 7 < s1; j += 8) {
        int    si[8];
        float4 r[8];
#pragma unroll
        for (int q = 0; q < 8; q++) si[q] = __ldg(&sorted[j + q]);
#pragma unroll
        for (int q = 0; q < 8; q++) r[q] = __ldg(base + (size_t)si[q] * 64 + foff);
        v.x += ((r[0].x + r[1].x) + (r[2].x + r[3].x)) + ((r[4].x + r[5].x) + (r[6].x + r[7].x));
        v.y += ((r[0].y + r[1].y) + (r[2].y + r[3].y)) + ((r[4].y + r[5].y) + (r[6].y + r[7].y));
        v.z += ((r[0].z + r[1].z) + (r[2].z + r[3].z)) + ((r[4].z + r[5].z) + (r[6].z + r[7].z));
        v.w += ((r[0].w + r[1].w) + (r[2].w + r[3].w)) + ((r[4].w + r[5].w) + (r[6].w + r[7].w));
    }
    for (; j < s1; j++) {
        int s = __ldg(&sorted[j]);
        float4 a = __ldg(base + (size_t)s * 64 + foff);
        v.x += a.x; v.y += a.y; v.z += a.z; v.w += a.w;
    }

    const float dd = dinv[d];
    v.x *= dd; v.y *= dd; v.z *= dd; v.w *= dd;
    reinterpret_cast<float4*>(z)[(size_t)d * 64 + foff] = v;
}

// ---------------------------------------------------------------------------
// Launch
// ---------------------------------------------------------------------------
extern "C" void kernel_launch(void* const* d_in, const int* in_sizes, int n_in,
                              void* d_out, int out_size) {
    const float* x  = (const float*)d_in[0];
    const int*   ei = (const int*)d_in[1];
    const float* W1 = (const float*)d_in[2];
    const float* b1 = (const float*)d_in[3];
    const float* W2 = (const float*)d_in[4];
    const float* b2 = (const float*)d_in[5];
    float* out = (float*)d_out;

    const int n = in_sizes[0] / DIN;
    const int e = in_sizes[1] / 2;
    const int* esrc = ei;
    const int* edst = ei + e;

    float *dinv, *buf1, *buf2, *wt1, *wt2;
    int *cnt, *off, *cur, *srt;
    cudaGetSymbolAddress((void**)&dinv, g_dinv);
    cudaGetSymbolAddress((void**)&buf1, g_buf1);
    cudaGetSymbolAddress((void**)&buf2, g_buf2);
    cudaGetSymbolAddress((void**)&cnt,  g_cnt);
    cudaGetSymbolAddress((void**)&off,  g_off);
    cudaGetSymbolAddress((void**)&cur,  g_cur);
    cudaGetSymbolAddress((void**)&srt,  g_src);
    cudaGetSymbolAddress((void**)&wt1,  g_wt1);
    cudaGetSymbolAddress((void**)&wt2,  g_wt2);

    cudaFuncSetAttribute(gemm_bmma_kernel<DIN, 0>, cudaFuncAttributeMaxDynamicSharedMemorySize, BMMA_SMEM);
    cudaFuncSetAttribute(gemm_bmma_kernel<DH, 1>,  cudaFuncAttributeMaxDynamicSharedMemorySize, BMMA_SMEM);

    const int T = 256;
    const int e_blk  = (e + T - 1) / T;
    const int gx_blk = (n + (T / 32) - 1) / (T / 32);       // 1 warp / node
    const int gh_blk = (2 * n + (T / 32) - 1) / (T / 32);   // 2 warps / node
    const int gemm_blk = (n + BMM - 1) / BMM;

    // ----- CSR build -----
    cudaMemsetAsync(cnt, 0, (size_t)n * sizeof(int));
    count_kernel<<<e_blk, T>>>(edst, e, cnt);
    scan_kernel<<<1, 1024>>>(cnt, off, cur, dinv, n);
    fill_kernel<<<e_blk, T>>>(esrc, edst, e, cur, srt);

    // ----- weight transposes -----
    transpose_kernel<DIN><<<dim3(DH / 32, DIN / 32), dim3(32, 8)>>>(W1, wt1);
    transpose_kernel<DH><<<dim3(DH / 32, DH / 32), dim3(32, 8)>>>(W2, wt2);

    // ----- Layer 1 (aggregate-first: 128-dim gather) -----
    gather_x_kernel<<<gx_blk, T>>>(x, off, srt, dinv, buf1, n);
    gemm_bmma_kernel<DIN, 0><<<gemm_blk, T, BMMA_SMEM>>>(buf1, wt1, dinv, b1, buf2, n);

    // ----- Layer 2 (aggregate-then-transform) -----
    gather_h_kernel<<<gh_blk, T>>>(buf2, off, srt, dinv, buf1, n);
    gemm_bmma_kernel<DH, 1><<<gemm_blk, T, BMMA_SMEM>>>(buf1, wt2, dinv, b2, out, n);
}